// round 5
// baseline (speedup 1.0000x reference)
#include <cuda_runtime.h>

#define HW_ 65536  // 256*256

// Scratch (allocation-free rule: __device__ globals)
__device__ float g_xcat[(size_t)2 * 128 * HW_];   // concat [x2, up]
__device__ float g_off[(size_t)2 * 256 * HW_];    // offset conv output
__device__ float g_xd[(size_t)2 * 128 * HW_];     // deformed gather
__device__ float g_y[(size_t)2 * 64 * HW_];       // conv pre-BN
__device__ float g_hbuf[(size_t)2 * 64 * HW_];    // post BN-ReLU
__device__ float g_scale[64];
__device__ float g_shift[64];

// ---------------------------------------------------------------------------
// ConvTranspose2d(64->64, k=2, s=2): up[b,o,2h+k,2w+l] = sum_i x1[b,i,h,w]*W[i,o,k,l]
// writes into channels [64,128) of g_xcat
// ---------------------------------------------------------------------------
__global__ void upconv_kernel(const float* __restrict__ x1,
                              const float* __restrict__ up_w,
                              const float* __restrict__ up_b) {
    int idx = blockIdx.x * blockDim.x + threadIdx.x;  // 2*64*128*128 threads
    int w = idx & 127;
    int t = idx >> 7;
    int h = t & 127;
    t >>= 7;
    int o = t & 63;
    int b = t >> 6;

    float a00 = 0.f, a01 = 0.f, a10 = 0.f, a11 = 0.f;
    const float* xp = x1 + (size_t)b * 64 * 128 * 128 + h * 128 + w;
#pragma unroll 4
    for (int i = 0; i < 64; i++) {
        float xv = xp[i * 128 * 128];
        float4 wv = *(const float4*)(up_w + ((size_t)i * 64 + o) * 4);
        a00 = fmaf(xv, wv.x, a00);
        a01 = fmaf(xv, wv.y, a01);
        a10 = fmaf(xv, wv.z, a10);
        a11 = fmaf(xv, wv.w, a11);
    }
    float bb = up_b[o];
    float* outp = g_xcat + (((size_t)b * 128 + 64 + o) * 256 + 2 * h) * 256 + 2 * w;
    *(float2*)outp = make_float2(a00 + bb, a01 + bb);
    *(float2*)(outp + 256) = make_float2(a10 + bb, a11 + bb);
}

// ---------------------------------------------------------------------------
// Tiled direct conv3x3, pad=1, stride=1 on 256x256 images.
// Block: 256 threads, 32x32 pixel tile, OCB=8 output channels, ICB=8 ic chunk.
// Thread (tx=tid&31, ty=tid>>5) computes rows {ty, ty+8, ty+16, ty+24}, col tx.
// ---------------------------------------------------------------------------
template <int CIN, int COUT, bool HAS_BIAS>
__global__ void __launch_bounds__(256) conv3x3_kernel(
    const float* __restrict__ in, const float* __restrict__ wgt,
    const float* __restrict__ bias, float* __restrict__ out) {
    constexpr int ICB = 8, OCB = 8;
    __shared__ float sIn[ICB][34][34];
    __shared__ float sW[OCB][ICB][9];

    const int tid = threadIdx.x;
    const int tx = tid & 31, ty = tid >> 5;
    const int tile_x = blockIdx.x * 32, tile_y = blockIdx.y * 32;
    const int nOG = COUT / OCB;
    const int og = blockIdx.z % nOG, b = blockIdx.z / nOG;
    const int oc0 = og * OCB;

    float acc[4][OCB];
#pragma unroll
    for (int oc = 0; oc < OCB; oc++) {
        float init = HAS_BIAS ? bias[oc0 + oc] : 0.f;
#pragma unroll
        for (int r = 0; r < 4; r++) acc[r][oc] = init;
    }

    const float* inb = in + (size_t)b * CIN * HW_;

    for (int ic0 = 0; ic0 < CIN; ic0 += ICB) {
        __syncthreads();
        // input tile (34x34 x ICB), zero-padded halo
        for (int i = tid; i < ICB * 34 * 34; i += 256) {
            int x = i % 34;
            int r2 = i / 34;
            int y = r2 % 34;
            int ic = r2 / 34;
            int gx = tile_x + x - 1, gy = tile_y + y - 1;
            float v = 0.f;
            if ((unsigned)gx < 256u && (unsigned)gy < 256u)
                v = inb[(size_t)(ic0 + ic) * HW_ + gy * 256 + gx];
            sIn[ic][y][x] = v;
        }
        // weights OCB x ICB x 9
        for (int i = tid; i < OCB * ICB * 9; i += 256) {
            int k = i % 9;
            int r2 = i / 9;
            int ic = r2 % ICB;
            int oc = r2 / ICB;
            sW[oc][ic][k] = wgt[((size_t)(oc0 + oc) * CIN + (ic0 + ic)) * 9 + k];
        }
        __syncthreads();

#pragma unroll
        for (int ic = 0; ic < ICB; ic++)
#pragma unroll
            for (int ky = 0; ky < 3; ky++)
#pragma unroll
                for (int kx = 0; kx < 3; kx++) {
                    float i0 = sIn[ic][ty + ky][tx + kx];
                    float i1 = sIn[ic][ty + 8 + ky][tx + kx];
                    float i2 = sIn[ic][ty + 16 + ky][tx + kx];
                    float i3 = sIn[ic][ty + 24 + ky][tx + kx];
#pragma unroll
                    for (int oc = 0; oc < OCB; oc++) {
                        float wv = sW[oc][ic][ky * 3 + kx];
                        acc[0][oc] = fmaf(i0, wv, acc[0][oc]);
                        acc[1][oc] = fmaf(i1, wv, acc[1][oc]);
                        acc[2][oc] = fmaf(i2, wv, acc[2][oc]);
                        acc[3][oc] = fmaf(i3, wv, acc[3][oc]);
                    }
                }
    }

#pragma unroll
    for (int oc = 0; oc < OCB; oc++) {
        float* op = out + ((size_t)b * COUT + oc0 + oc) * HW_ +
                    (size_t)(tile_y + ty) * 256 + tile_x + tx;
        op[0 * 8 * 256] = acc[0][oc];
        op[1 * 8 * 256] = acc[1][oc];
        op[2 * 8 * 256] = acc[2][oc];
        op[3 * 8 * 256] = acc[3][oc];
    }
}

// ---------------------------------------------------------------------------
// Deformable bilinear gather.
// offsets.reshape(B*C,H,W,2) element (b,c,h,w,j) lives at flat index
//   (b*2C + 2c)*HW + 2*(h*W+w) + j   in the raw (B,2C,H,W) conv output.
// ---------------------------------------------------------------------------
__global__ void gather_kernel() {
    int idx = blockIdx.x * blockDim.x + threadIdx.x;  // 2*128*HW threads
    int w = idx & 255;
    int t = idx >> 8;
    int h = t & 255;
    t >>= 8;
    int c = t & 127;
    int b = t >> 7;

    int P = (h << 8) | w;
    const float* offp = g_off + (((size_t)b * 256 + 2 * c) << 16);
    float off0 = offp[2 * P];
    float off1 = offp[2 * P + 1];

    float cy = fminf(fmaxf(off0 + (float)h, 0.f), 255.f);
    float cx = fminf(fmaxf(off1 + (float)w, 0.f), 255.f);
    float y0f = floorf(cy), x0f = floorf(cx);
    int y0 = (int)y0f, x0 = (int)x0f;
    int y1 = (int)ceilf(cy), x1 = (int)ceilf(cx);

    const float* xc = g_xcat + (((size_t)b * 128 + c) << 16);
    float v00 = xc[(y0 << 8) + x0];
    float v10 = xc[(y1 << 8) + x0];
    float v01 = xc[(y0 << 8) + x1];
    float v11 = xc[(y1 << 8) + x1];

    float wy = cy - y0f, wx = cx - x0f;
    float vt = v00 + (v10 - v00) * wy;
    float vb = v01 + (v11 - v01) * wy;
    g_xd[idx] = vt + (vb - vt) * wx;
}

// ---------------------------------------------------------------------------
// BatchNorm (training stats over N,H,W): one block per channel, deterministic.
// ---------------------------------------------------------------------------
__global__ void bn_stats_kernel(const float* __restrict__ y,
                                const float* __restrict__ gamma,
                                const float* __restrict__ beta) {
    int c = blockIdx.x;  // 0..63
    __shared__ float ss[256], sq[256];
    float s = 0.f, q = 0.f;
    for (int b = 0; b < 2; b++) {
        const float* p = y + ((size_t)b * 64 + c) * HW_;
        for (int i = threadIdx.x; i < HW_; i += 256) {
            float v = p[i];
            s += v;
            q += v * v;
        }
    }
    ss[threadIdx.x] = s;
    sq[threadIdx.x] = q;
    __syncthreads();
    for (int off = 128; off > 0; off >>= 1) {
        if (threadIdx.x < off) {
            ss[threadIdx.x] += ss[threadIdx.x + off];
            sq[threadIdx.x] += sq[threadIdx.x + off];
        }
        __syncthreads();
    }
    if (threadIdx.x == 0) {
        const float inv = 1.f / 131072.f;
        float m = ss[0] * inv;
        float var = sq[0] * inv - m * m;
        float r = rsqrtf(var + 1e-5f);
        float sc = gamma[c] * r;
        g_scale[c] = sc;
        g_shift[c] = beta[c] - m * sc;
    }
}

__global__ void bn_apply_kernel(const float* __restrict__ y, float* __restrict__ out) {
    int idx = blockIdx.x * blockDim.x + threadIdx.x;  // over total/4 float4s
    int c = (idx >> 14) & 63;                         // HW_/4 = 16384 vec4 per channel
    float sc = g_scale[c], sh = g_shift[c];
    float4 v = ((const float4*)y)[idx];
    float4 r;
    r.x = fmaxf(0.f, fmaf(v.x, sc, sh));
    r.y = fmaxf(0.f, fmaf(v.y, sc, sh));
    r.z = fmaxf(0.f, fmaf(v.z, sc, sh));
    r.w = fmaxf(0.f, fmaf(v.w, sc, sh));
    ((float4*)out)[idx] = r;
}

// ---------------------------------------------------------------------------
extern "C" void kernel_launch(void* const* d_in, const int* in_sizes, int n_in,
                              void* d_out, int out_size) {
    const float* x1 = (const float*)d_in[0];
    const float* x2 = (const float*)d_in[1];
    const float* up_w = (const float*)d_in[2];
    const float* up_b = (const float*)d_in[3];
    const float* off_w = (const float*)d_in[4];
    const float* c1_w = (const float*)d_in[5];
    const float* c1_b = (const float*)d_in[6];
    const float* g1 = (const float*)d_in[7];
    const float* b1 = (const float*)d_in[8];
    const float* c2_w = (const float*)d_in[9];
    const float* c2_b = (const float*)d_in[10];
    const float* g2 = (const float*)d_in[11];
    const float* b2 = (const float*)d_in[12];
    float* out = (float*)d_out;

    float* xcat_ptr;
    float* off_ptr;
    float* xd_ptr;
    float* y_ptr;
    float* h_ptr;
    cudaGetSymbolAddress((void**)&xcat_ptr, g_xcat);
    cudaGetSymbolAddress((void**)&off_ptr, g_off);
    cudaGetSymbolAddress((void**)&xd_ptr, g_xd);
    cudaGetSymbolAddress((void**)&y_ptr, g_y);
    cudaGetSymbolAddress((void**)&h_ptr, g_hbuf);

    // 1) upsample into xcat[:,64:128) + copy skip into xcat[:,0:64)
    upconv_kernel<<<(2 * 64 * 128 * 128) / 256, 256>>>(x1, up_w, up_b);
    for (int b = 0; b < 2; b++)
        cudaMemcpyAsync(xcat_ptr + (size_t)b * 128 * HW_, x2 + (size_t)b * 64 * HW_,
                        (size_t)64 * HW_ * sizeof(float), cudaMemcpyDeviceToDevice, 0);

    // 2) offset conv (128 -> 256 channels, no bias)
    conv3x3_kernel<128, 256, false><<<dim3(8, 8, 2 * 32), 256>>>(xcat_ptr, off_w, nullptr, off_ptr);

    // 3) deformable bilinear gather
    gather_kernel<<<65536, 256>>>();

    // 4) conv1 + BN + ReLU
    conv3x3_kernel<128, 64, true><<<dim3(8, 8, 2 * 8), 256>>>(xd_ptr, c1_w, c1_b, y_ptr);
    bn_stats_kernel<<<64, 256>>>(y_ptr, g1, b1);
    bn_apply_kernel<<<8192, 256>>>(y_ptr, h_ptr);

    // 5) conv2 + BN + ReLU -> output
    conv3x3_kernel<64, 64, true><<<dim3(8, 8, 2 * 8), 256>>>(h_ptr, c2_w, c2_b, y_ptr);
    bn_stats_kernel<<<64, 256>>>(y_ptr, g2, b2);
    bn_apply_kernel<<<8192, 256>>>(y_ptr, out);
}

// round 6
// speedup vs baseline: 1.0028x; 1.0028x over previous
#include <cuda_runtime.h>

#define HW_ 65536  // 256*256

// Scratch (allocation-free rule: __device__ globals)
__device__ float g_xcat[(size_t)2 * 128 * HW_];   // concat [x2, up]
__device__ float g_off[(size_t)2 * 256 * HW_];    // offset conv output
__device__ float g_xd[(size_t)2 * 128 * HW_];     // deformed gather
__device__ float g_y[(size_t)2 * 64 * HW_];       // conv pre-BN
__device__ float g_hbuf[(size_t)2 * 64 * HW_];    // post BN-ReLU
__device__ float g_scale[64];
__device__ float g_shift[64];

// ---------------------------------------------------------------------------
// ConvTranspose2d(64->64, k=2, s=2): up[b,o,2h+k,2w+l] = sum_i x1[b,i,h,w]*W[i,o,k,l]
// writes into channels [64,128) of g_xcat
// ---------------------------------------------------------------------------
__global__ void upconv_kernel(const float* __restrict__ x1,
                              const float* __restrict__ up_w,
                              const float* __restrict__ up_b) {
    int idx = blockIdx.x * blockDim.x + threadIdx.x;  // 2*64*128*128 threads
    int w = idx & 127;
    int t = idx >> 7;
    int h = t & 127;
    t >>= 7;
    int o = t & 63;
    int b = t >> 6;

    float a00 = 0.f, a01 = 0.f, a10 = 0.f, a11 = 0.f;
    const float* xp = x1 + (size_t)b * 64 * 128 * 128 + h * 128 + w;
#pragma unroll 4
    for (int i = 0; i < 64; i++) {
        float xv = xp[i * 128 * 128];
        float4 wv = *(const float4*)(up_w + ((size_t)i * 64 + o) * 4);
        a00 = fmaf(xv, wv.x, a00);
        a01 = fmaf(xv, wv.y, a01);
        a10 = fmaf(xv, wv.z, a10);
        a11 = fmaf(xv, wv.w, a11);
    }
    float bb = up_b[o];
    float* outp = g_xcat + (((size_t)b * 128 + 64 + o) * 256 + 2 * h) * 256 + 2 * w;
    *(float2*)outp = make_float2(a00 + bb, a01 + bb);
    *(float2*)(outp + 256) = make_float2(a10 + bb, a11 + bb);
}

// ---------------------------------------------------------------------------
// Tiled direct conv3x3, pad=1, stride=1 on 256x256 images.
// Block: 256 threads, 32x32 pixel tile, OCB=8 output channels, ICB=8 ic chunk.
// Thread (tx=tid&31, ty=tid>>5) computes rows {ty, ty+8, ty+16, ty+24}, col tx.
// ---------------------------------------------------------------------------
template <int CIN, int COUT, bool HAS_BIAS>
__global__ void __launch_bounds__(256) conv3x3_kernel(
    const float* __restrict__ in, const float* __restrict__ wgt,
    const float* __restrict__ bias, float* __restrict__ out) {
    constexpr int ICB = 8, OCB = 8;
    __shared__ float sIn[ICB][34][34];
    __shared__ float sW[OCB][ICB][9];

    const int tid = threadIdx.x;
    const int tx = tid & 31, ty = tid >> 5;
    const int tile_x = blockIdx.x * 32, tile_y = blockIdx.y * 32;
    const int nOG = COUT / OCB;
    const int og = blockIdx.z % nOG, b = blockIdx.z / nOG;
    const int oc0 = og * OCB;

    float acc[4][OCB];
#pragma unroll
    for (int oc = 0; oc < OCB; oc++) {
        float init = HAS_BIAS ? bias[oc0 + oc] : 0.f;
#pragma unroll
        for (int r = 0; r < 4; r++) acc[r][oc] = init;
    }

    const float* inb = in + (size_t)b * CIN * HW_;

    for (int ic0 = 0; ic0 < CIN; ic0 += ICB) {
        __syncthreads();
        // input tile (34x34 x ICB), zero-padded halo
        for (int i = tid; i < ICB * 34 * 34; i += 256) {
            int x = i % 34;
            int r2 = i / 34;
            int y = r2 % 34;
            int ic = r2 / 34;
            int gx = tile_x + x - 1, gy = tile_y + y - 1;
            float v = 0.f;
            if ((unsigned)gx < 256u && (unsigned)gy < 256u)
                v = inb[(size_t)(ic0 + ic) * HW_ + gy * 256 + gx];
            sIn[ic][y][x] = v;
        }
        // weights OCB x ICB x 9
        for (int i = tid; i < OCB * ICB * 9; i += 256) {
            int k = i % 9;
            int r2 = i / 9;
            int ic = r2 % ICB;
            int oc = r2 / ICB;
            sW[oc][ic][k] = wgt[((size_t)(oc0 + oc) * CIN + (ic0 + ic)) * 9 + k];
        }
        __syncthreads();

#pragma unroll
        for (int ic = 0; ic < ICB; ic++)
#pragma unroll
            for (int ky = 0; ky < 3; ky++)
#pragma unroll
                for (int kx = 0; kx < 3; kx++) {
                    float i0 = sIn[ic][ty + ky][tx + kx];
                    float i1 = sIn[ic][ty + 8 + ky][tx + kx];
                    float i2 = sIn[ic][ty + 16 + ky][tx + kx];
                    float i3 = sIn[ic][ty + 24 + ky][tx + kx];
#pragma unroll
                    for (int oc = 0; oc < OCB; oc++) {
                        float wv = sW[oc][ic][ky * 3 + kx];
                        acc[0][oc] = fmaf(i0, wv, acc[0][oc]);
                        acc[1][oc] = fmaf(i1, wv, acc[1][oc]);
                        acc[2][oc] = fmaf(i2, wv, acc[2][oc]);
                        acc[3][oc] = fmaf(i3, wv, acc[3][oc]);
                    }
                }
    }

#pragma unroll
    for (int oc = 0; oc < OCB; oc++) {
        float* op = out + ((size_t)b * COUT + oc0 + oc) * HW_ +
                    (size_t)(tile_y + ty) * 256 + tile_x + tx;
        op[0 * 8 * 256] = acc[0][oc];
        op[1 * 8 * 256] = acc[1][oc];
        op[2 * 8 * 256] = acc[2][oc];
        op[3 * 8 * 256] = acc[3][oc];
    }
}

// ---------------------------------------------------------------------------
// Deformable bilinear gather.
// offsets.reshape(B*C,H,W,2) element (b,c,h,w,j) lives at flat index
//   (b*2C + 2c)*HW + 2*(h*W+w) + j   in the raw (B,2C,H,W) conv output.
// ---------------------------------------------------------------------------
__global__ void gather_kernel() {
    int idx = blockIdx.x * blockDim.x + threadIdx.x;  // 2*128*HW threads
    int w = idx & 255;
    int t = idx >> 8;
    int h = t & 255;
    t >>= 8;
    int c = t & 127;
    int b = t >> 7;

    int P = (h << 8) | w;
    const float* offp = g_off + (((size_t)b * 256 + 2 * c) << 16);
    float off0 = offp[2 * P];
    float off1 = offp[2 * P + 1];

    float cy = fminf(fmaxf(off0 + (float)h, 0.f), 255.f);
    float cx = fminf(fmaxf(off1 + (float)w, 0.f), 255.f);
    float y0f = floorf(cy), x0f = floorf(cx);
    int y0 = (int)y0f, x0 = (int)x0f;
    int y1 = (int)ceilf(cy), x1 = (int)ceilf(cx);

    const float* xc = g_xcat + (((size_t)b * 128 + c) << 16);
    float v00 = xc[(y0 << 8) + x0];
    float v10 = xc[(y1 << 8) + x0];
    float v01 = xc[(y0 << 8) + x1];
    float v11 = xc[(y1 << 8) + x1];

    float wy = cy - y0f, wx = cx - x0f;
    float vt = v00 + (v10 - v00) * wy;
    float vb = v01 + (v11 - v01) * wy;
    g_xd[idx] = vt + (vb - vt) * wx;
}

// ---------------------------------------------------------------------------
// BatchNorm (training stats over N,H,W): one block per channel, deterministic.
// ---------------------------------------------------------------------------
__global__ void bn_stats_kernel(const float* __restrict__ y,
                                const float* __restrict__ gamma,
                                const float* __restrict__ beta) {
    int c = blockIdx.x;  // 0..63
    __shared__ float ss[256], sq[256];
    float s = 0.f, q = 0.f;
    for (int b = 0; b < 2; b++) {
        const float* p = y + ((size_t)b * 64 + c) * HW_;
        for (int i = threadIdx.x; i < HW_; i += 256) {
            float v = p[i];
            s += v;
            q += v * v;
        }
    }
    ss[threadIdx.x] = s;
    sq[threadIdx.x] = q;
    __syncthreads();
    for (int off = 128; off > 0; off >>= 1) {
        if (threadIdx.x < off) {
            ss[threadIdx.x] += ss[threadIdx.x + off];
            sq[threadIdx.x] += sq[threadIdx.x + off];
        }
        __syncthreads();
    }
    if (threadIdx.x == 0) {
        const float inv = 1.f / 131072.f;
        float m = ss[0] * inv;
        float var = sq[0] * inv - m * m;
        float r = rsqrtf(var + 1e-5f);
        float sc = gamma[c] * r;
        g_scale[c] = sc;
        g_shift[c] = beta[c] - m * sc;
    }
}

__global__ void bn_apply_kernel(const float* __restrict__ y, float* __restrict__ out) {
    int idx = blockIdx.x * blockDim.x + threadIdx.x;  // over total/4 float4s
    int c = (idx >> 14) & 63;                         // HW_/4 = 16384 vec4 per channel
    float sc = g_scale[c], sh = g_shift[c];
    float4 v = ((const float4*)y)[idx];
    float4 r;
    r.x = fmaxf(0.f, fmaf(v.x, sc, sh));
    r.y = fmaxf(0.f, fmaf(v.y, sc, sh));
    r.z = fmaxf(0.f, fmaf(v.z, sc, sh));
    r.w = fmaxf(0.f, fmaf(v.w, sc, sh));
    ((float4*)out)[idx] = r;
}

// ---------------------------------------------------------------------------
extern "C" void kernel_launch(void* const* d_in, const int* in_sizes, int n_in,
                              void* d_out, int out_size) {
    const float* x1 = (const float*)d_in[0];
    const float* x2 = (const float*)d_in[1];
    const float* up_w = (const float*)d_in[2];
    const float* up_b = (const float*)d_in[3];
    const float* off_w = (const float*)d_in[4];
    const float* c1_w = (const float*)d_in[5];
    const float* c1_b = (const float*)d_in[6];
    const float* g1 = (const float*)d_in[7];
    const float* b1 = (const float*)d_in[8];
    const float* c2_w = (const float*)d_in[9];
    const float* c2_b = (const float*)d_in[10];
    const float* g2 = (const float*)d_in[11];
    const float* b2 = (const float*)d_in[12];
    float* out = (float*)d_out;

    float* xcat_ptr;
    float* off_ptr;
    float* xd_ptr;
    float* y_ptr;
    float* h_ptr;
    cudaGetSymbolAddress((void**)&xcat_ptr, g_xcat);
    cudaGetSymbolAddress((void**)&off_ptr, g_off);
    cudaGetSymbolAddress((void**)&xd_ptr, g_xd);
    cudaGetSymbolAddress((void**)&y_ptr, g_y);
    cudaGetSymbolAddress((void**)&h_ptr, g_hbuf);

    // 1) upsample into xcat[:,64:128) + copy skip into xcat[:,0:64)
    upconv_kernel<<<(2 * 64 * 128 * 128) / 256, 256>>>(x1, up_w, up_b);
    for (int b = 0; b < 2; b++)
        cudaMemcpyAsync(xcat_ptr + (size_t)b * 128 * HW_, x2 + (size_t)b * 64 * HW_,
                        (size_t)64 * HW_ * sizeof(float), cudaMemcpyDeviceToDevice, 0);

    // 2) offset conv (128 -> 256 channels, no bias)
    conv3x3_kernel<128, 256, false><<<dim3(8, 8, 2 * 32), 256>>>(xcat_ptr, off_w, nullptr, off_ptr);

    // 3) deformable bilinear gather
    gather_kernel<<<65536, 256>>>();

    // 4) conv1 + BN + ReLU
    conv3x3_kernel<128, 64, true><<<dim3(8, 8, 2 * 8), 256>>>(xd_ptr, c1_w, c1_b, y_ptr);
    bn_stats_kernel<<<64, 256>>>(y_ptr, g1, b1);
    bn_apply_kernel<<<8192, 256>>>(y_ptr, h_ptr);

    // 5) conv2 + BN + ReLU -> output
    conv3x3_kernel<64, 64, true><<<dim3(8, 8, 2 * 8), 256>>>(h_ptr, c2_w, c2_b, y_ptr);
    bn_stats_kernel<<<64, 256>>>(y_ptr, g2, b2);
    bn_apply_kernel<<<8192, 256>>>(y_ptr, out);
}

// round 7
// speedup vs baseline: 1.0037x; 1.0009x over previous
#include <cuda_runtime.h>

#define HW_ 65536  // 256*256

// Scratch (allocation-free rule: __device__ globals)
__device__ float g_xcat[(size_t)2 * 128 * HW_];   // concat [x2, up]
__device__ float g_off[(size_t)2 * 256 * HW_];    // offset conv output
__device__ float g_xd[(size_t)2 * 128 * HW_];     // deformed gather
__device__ float g_y[(size_t)2 * 64 * HW_];       // conv pre-BN
__device__ float g_hbuf[(size_t)2 * 64 * HW_];    // post BN-ReLU
__device__ float g_scale[64];
__device__ float g_shift[64];

// ---------------------------------------------------------------------------
// ConvTranspose2d(64->64, k=2, s=2): up[b,o,2h+k,2w+l] = sum_i x1[b,i,h,w]*W[i,o,k,l]
// writes into channels [64,128) of g_xcat
// ---------------------------------------------------------------------------
__global__ void upconv_kernel(const float* __restrict__ x1,
                              const float* __restrict__ up_w,
                              const float* __restrict__ up_b) {
    int idx = blockIdx.x * blockDim.x + threadIdx.x;  // 2*64*128*128 threads
    int w = idx & 127;
    int t = idx >> 7;
    int h = t & 127;
    t >>= 7;
    int o = t & 63;
    int b = t >> 6;

    float a00 = 0.f, a01 = 0.f, a10 = 0.f, a11 = 0.f;
    const float* xp = x1 + (size_t)b * 64 * 128 * 128 + h * 128 + w;
#pragma unroll 4
    for (int i = 0; i < 64; i++) {
        float xv = xp[i * 128 * 128];
        float4 wv = *(const float4*)(up_w + ((size_t)i * 64 + o) * 4);
        a00 = fmaf(xv, wv.x, a00);
        a01 = fmaf(xv, wv.y, a01);
        a10 = fmaf(xv, wv.z, a10);
        a11 = fmaf(xv, wv.w, a11);
    }
    float bb = up_b[o];
    float* outp = g_xcat + (((size_t)b * 128 + 64 + o) * 256 + 2 * h) * 256 + 2 * w;
    *(float2*)outp = make_float2(a00 + bb, a01 + bb);
    *(float2*)(outp + 256) = make_float2(a10 + bb, a11 + bb);
}

// ---------------------------------------------------------------------------
// Tiled direct conv3x3, pad=1, stride=1 on 256x256 images.
// Block: 256 threads, 32x32 pixel tile, OCB=8 output channels, ICB=8 ic chunk.
// Thread (tx=tid&31, ty=tid>>5) computes rows {ty, ty+8, ty+16, ty+24}, col tx.
// ---------------------------------------------------------------------------
template <int CIN, int COUT, bool HAS_BIAS>
__global__ void __launch_bounds__(256) conv3x3_kernel(
    const float* __restrict__ in, const float* __restrict__ wgt,
    const float* __restrict__ bias, float* __restrict__ out) {
    constexpr int ICB = 8, OCB = 8;
    __shared__ float sIn[ICB][34][34];
    __shared__ float sW[OCB][ICB][9];

    const int tid = threadIdx.x;
    const int tx = tid & 31, ty = tid >> 5;
    const int tile_x = blockIdx.x * 32, tile_y = blockIdx.y * 32;
    const int nOG = COUT / OCB;
    const int og = blockIdx.z % nOG, b = blockIdx.z / nOG;
    const int oc0 = og * OCB;

    float acc[4][OCB];
#pragma unroll
    for (int oc = 0; oc < OCB; oc++) {
        float init = HAS_BIAS ? bias[oc0 + oc] : 0.f;
#pragma unroll
        for (int r = 0; r < 4; r++) acc[r][oc] = init;
    }

    const float* inb = in + (size_t)b * CIN * HW_;

    for (int ic0 = 0; ic0 < CIN; ic0 += ICB) {
        __syncthreads();
        // input tile (34x34 x ICB), zero-padded halo
        for (int i = tid; i < ICB * 34 * 34; i += 256) {
            int x = i % 34;
            int r2 = i / 34;
            int y = r2 % 34;
            int ic = r2 / 34;
            int gx = tile_x + x - 1, gy = tile_y + y - 1;
            float v = 0.f;
            if ((unsigned)gx < 256u && (unsigned)gy < 256u)
                v = inb[(size_t)(ic0 + ic) * HW_ + gy * 256 + gx];
            sIn[ic][y][x] = v;
        }
        // weights OCB x ICB x 9
        for (int i = tid; i < OCB * ICB * 9; i += 256) {
            int k = i % 9;
            int r2 = i / 9;
            int ic = r2 % ICB;
            int oc = r2 / ICB;
            sW[oc][ic][k] = wgt[((size_t)(oc0 + oc) * CIN + (ic0 + ic)) * 9 + k];
        }
        __syncthreads();

#pragma unroll
        for (int ic = 0; ic < ICB; ic++)
#pragma unroll
            for (int ky = 0; ky < 3; ky++)
#pragma unroll
                for (int kx = 0; kx < 3; kx++) {
                    float i0 = sIn[ic][ty + ky][tx + kx];
                    float i1 = sIn[ic][ty + 8 + ky][tx + kx];
                    float i2 = sIn[ic][ty + 16 + ky][tx + kx];
                    float i3 = sIn[ic][ty + 24 + ky][tx + kx];
#pragma unroll
                    for (int oc = 0; oc < OCB; oc++) {
                        float wv = sW[oc][ic][ky * 3 + kx];
                        acc[0][oc] = fmaf(i0, wv, acc[0][oc]);
                        acc[1][oc] = fmaf(i1, wv, acc[1][oc]);
                        acc[2][oc] = fmaf(i2, wv, acc[2][oc]);
                        acc[3][oc] = fmaf(i3, wv, acc[3][oc]);
                    }
                }
    }

#pragma unroll
    for (int oc = 0; oc < OCB; oc++) {
        float* op = out + ((size_t)b * COUT + oc0 + oc) * HW_ +
                    (size_t)(tile_y + ty) * 256 + tile_x + tx;
        op[0 * 8 * 256] = acc[0][oc];
        op[1 * 8 * 256] = acc[1][oc];
        op[2 * 8 * 256] = acc[2][oc];
        op[3 * 8 * 256] = acc[3][oc];
    }
}

// ---------------------------------------------------------------------------
// Deformable bilinear gather.
// offsets.reshape(B*C,H,W,2) element (b,c,h,w,j) lives at flat index
//   (b*2C + 2c)*HW + 2*(h*W+w) + j   in the raw (B,2C,H,W) conv output.
// ---------------------------------------------------------------------------
__global__ void gather_kernel() {
    int idx = blockIdx.x * blockDim.x + threadIdx.x;  // 2*128*HW threads
    int w = idx & 255;
    int t = idx >> 8;
    int h = t & 255;
    t >>= 8;
    int c = t & 127;
    int b = t >> 7;

    int P = (h << 8) | w;
    const float* offp = g_off + (((size_t)b * 256 + 2 * c) << 16);
    float off0 = offp[2 * P];
    float off1 = offp[2 * P + 1];

    float cy = fminf(fmaxf(off0 + (float)h, 0.f), 255.f);
    float cx = fminf(fmaxf(off1 + (float)w, 0.f), 255.f);
    float y0f = floorf(cy), x0f = floorf(cx);
    int y0 = (int)y0f, x0 = (int)x0f;
    int y1 = (int)ceilf(cy), x1 = (int)ceilf(cx);

    const float* xc = g_xcat + (((size_t)b * 128 + c) << 16);
    float v00 = xc[(y0 << 8) + x0];
    float v10 = xc[(y1 << 8) + x0];
    float v01 = xc[(y0 << 8) + x1];
    float v11 = xc[(y1 << 8) + x1];

    float wy = cy - y0f, wx = cx - x0f;
    float vt = v00 + (v10 - v00) * wy;
    float vb = v01 + (v11 - v01) * wy;
    g_xd[idx] = vt + (vb - vt) * wx;
}

// ---------------------------------------------------------------------------
// BatchNorm (training stats over N,H,W): one block per channel, deterministic.
// ---------------------------------------------------------------------------
__global__ void bn_stats_kernel(const float* __restrict__ y,
                                const float* __restrict__ gamma,
                                const float* __restrict__ beta) {
    int c = blockIdx.x;  // 0..63
    __shared__ float ss[256], sq[256];
    float s = 0.f, q = 0.f;
    for (int b = 0; b < 2; b++) {
        const float* p = y + ((size_t)b * 64 + c) * HW_;
        for (int i = threadIdx.x; i < HW_; i += 256) {
            float v = p[i];
            s += v;
            q += v * v;
        }
    }
    ss[threadIdx.x] = s;
    sq[threadIdx.x] = q;
    __syncthreads();
    for (int off = 128; off > 0; off >>= 1) {
        if (threadIdx.x < off) {
            ss[threadIdx.x] += ss[threadIdx.x + off];
            sq[threadIdx.x] += sq[threadIdx.x + off];
        }
        __syncthreads();
    }
    if (threadIdx.x == 0) {
        const float inv = 1.f / 131072.f;
        float m = ss[0] * inv;
        float var = sq[0] * inv - m * m;
        float r = rsqrtf(var + 1e-5f);
        float sc = gamma[c] * r;
        g_scale[c] = sc;
        g_shift[c] = beta[c] - m * sc;
    }
}

__global__ void bn_apply_kernel(const float* __restrict__ y, float* __restrict__ out) {
    int idx = blockIdx.x * blockDim.x + threadIdx.x;  // over total/4 float4s
    int c = (idx >> 14) & 63;                         // HW_/4 = 16384 vec4 per channel
    float sc = g_scale[c], sh = g_shift[c];
    float4 v = ((const float4*)y)[idx];
    float4 r;
    r.x = fmaxf(0.f, fmaf(v.x, sc, sh));
    r.y = fmaxf(0.f, fmaf(v.y, sc, sh));
    r.z = fmaxf(0.f, fmaf(v.z, sc, sh));
    r.w = fmaxf(0.f, fmaf(v.w, sc, sh));
    ((float4*)out)[idx] = r;
}

// ---------------------------------------------------------------------------
extern "C" void kernel_launch(void* const* d_in, const int* in_sizes, int n_in,
                              void* d_out, int out_size) {
    const float* x1 = (const float*)d_in[0];
    const float* x2 = (const float*)d_in[1];
    const float* up_w = (const float*)d_in[2];
    const float* up_b = (const float*)d_in[3];
    const float* off_w = (const float*)d_in[4];
    const float* c1_w = (const float*)d_in[5];
    const float* c1_b = (const float*)d_in[6];
    const float* g1 = (const float*)d_in[7];
    const float* b1 = (const float*)d_in[8];
    const float* c2_w = (const float*)d_in[9];
    const float* c2_b = (const float*)d_in[10];
    const float* g2 = (const float*)d_in[11];
    const float* b2 = (const float*)d_in[12];
    float* out = (float*)d_out;

    float* xcat_ptr;
    float* off_ptr;
    float* xd_ptr;
    float* y_ptr;
    float* h_ptr;
    cudaGetSymbolAddress((void**)&xcat_ptr, g_xcat);
    cudaGetSymbolAddress((void**)&off_ptr, g_off);
    cudaGetSymbolAddress((void**)&xd_ptr, g_xd);
    cudaGetSymbolAddress((void**)&y_ptr, g_y);
    cudaGetSymbolAddress((void**)&h_ptr, g_hbuf);

    // 1) upsample into xcat[:,64:128) + copy skip into xcat[:,0:64)
    upconv_kernel<<<(2 * 64 * 128 * 128) / 256, 256>>>(x1, up_w, up_b);
    for (int b = 0; b < 2; b++)
        cudaMemcpyAsync(xcat_ptr + (size_t)b * 128 * HW_, x2 + (size_t)b * 64 * HW_,
                        (size_t)64 * HW_ * sizeof(float), cudaMemcpyDeviceToDevice, 0);

    // 2) offset conv (128 -> 256 channels, no bias)
    conv3x3_kernel<128, 256, false><<<dim3(8, 8, 2 * 32), 256>>>(xcat_ptr, off_w, nullptr, off_ptr);

    // 3) deformable bilinear gather
    gather_kernel<<<65536, 256>>>();

    // 4) conv1 + BN + ReLU
    conv3x3_kernel<128, 64, true><<<dim3(8, 8, 2 * 8), 256>>>(xd_ptr, c1_w, c1_b, y_ptr);
    bn_stats_kernel<<<64, 256>>>(y_ptr, g1, b1);
    bn_apply_kernel<<<8192, 256>>>(y_ptr, h_ptr);

    // 5) conv2 + BN + ReLU -> output
    conv3x3_kernel<64, 64, true><<<dim3(8, 8, 2 * 8), 256>>>(h_ptr, c2_w, c2_b, y_ptr);
    bn_stats_kernel<<<64, 256>>>(y_ptr, g2, b2);
    bn_apply_kernel<<<8192, 256>>>(y_ptr, out);
}